// round 5
// baseline (speedup 1.0000x reference)
#include <cuda_runtime.h>
#include <cuda_fp16.h>
#include <mma.h>
#include <math.h>

using namespace nvcuda;

#define BB    16
#define NN    1024
#define UU    64
#define F1    128          // 2U
#define MTOT  (BB*NN)      // 16384
#define MAXD  128
#define ALPHA 0.2f

// ---------------- scratch (device globals; no allocation) ----------------
__device__ __half g_h1h[MTOT * F1];     // 4 MB  fp16 gather payload, layer 1
__device__ __half g_h2h[MTOT * UU];     // 2 MB  fp16 gather payload, layer 2
__device__ float  g_ssrc1[MTOT];
__device__ float  g_sdst1[MTOT];
__device__ float  g_ssrc2[MTOT];
__device__ float  g_sdst2[MTOT];
__device__ float  g_rstate[MTOT * UU];  // 4 MB (r * state)
__device__ float  g_z[MTOT * UU];       // 4 MB
__device__ int    g_nbr[NN * MAXD];     // 512 KB
__device__ int    g_deg[NN];

// ---------------- build sparse neighbor lists (deterministic order) ------
__global__ void build_adj_kernel(const float* __restrict__ adj) {
    int warp = (blockIdx.x * blockDim.x + threadIdx.x) >> 5;
    int lane = threadIdx.x & 31;
    if (warp >= NN) return;
    int base = 0;
    for (int j0 = 0; j0 < NN; j0 += 32) {
        float v = adj[warp * NN + j0 + lane];
        unsigned mask = __ballot_sync(0xffffffffu, v > 0.0f);
        if (v > 0.0f) {
            int pos = base + __popc(mask & ((1u << lane) - 1u));
            if (pos < MAXD) g_nbr[warp * MAXD + pos] = j0 + lane;
        }
        base += __popc(mask);
    }
    if (lane == 0) g_deg[warp] = base < MAXD ? base : MAXD;
}

// ---------------- GEMM1 (HMMA): h1[64x128 tile] = [X|state] @ W1 ---------
// 256 threads, 8 warps. warp w: rows (w>>1)*16, cols (w&1)*64 (4 frags).
// smem: A 64x128 half (16KB) + B 128x128 half (32KB) = 48KB; C reuses it.
__global__ void gemm1_kernel(const float* __restrict__ X,
                             const float* __restrict__ state,
                             const float* __restrict__ W1,
                             const float* __restrict__ a1) {
    __shared__ __align__(16) char smem[49152];
    __half* As = (__half*)smem;                 // [64][128]
    __half* Bs = (__half*)(smem + 16384);       // [128][128]
    float*  Cs = (float*)smem;                  // [64][136] after sync

    int tid = threadIdx.x;
    int m0 = blockIdx.x * 64;

    // stage A (convert fp32 -> fp16): 2048 float4 slots
    #pragma unroll
    for (int i = 0; i < 8; i++) {
        int idx = tid + 256 * i;
        int r = idx >> 5, s = idx & 31;
        int k0 = s * 4;
        int m = m0 + r;
        float4 v = (k0 < 64) ? *(const float4*)&X[(size_t)m * 64 + k0]
                             : *(const float4*)&state[(size_t)m * 64 + k0 - 64];
        __half2* dst = (__half2*)&As[r * 128 + k0];
        dst[0] = __floats2half2_rn(v.x, v.y);
        dst[1] = __floats2half2_rn(v.z, v.w);
    }
    // stage B: 4096 float4 slots
    #pragma unroll
    for (int i = 0; i < 16; i++) {
        int idx = tid + 256 * i;
        int kk = idx >> 5, s = idx & 31;
        int n0 = s * 4;
        float4 v = *(const float4*)&W1[(size_t)kk * 128 + n0];
        __half2* dst = (__half2*)&Bs[kk * 128 + n0];
        dst[0] = __floats2half2_rn(v.x, v.y);
        dst[1] = __floats2half2_rn(v.z, v.w);
    }
    __syncthreads();

    int w = tid >> 5;
    int rg = w >> 1;            // row group 0..3 -> rows rg*16
    int ch = w & 1;             // col half 0..1 -> cols ch*64

    wmma::fragment<wmma::accumulator, 16, 16, 16, float> cf[4];
    #pragma unroll
    for (int j = 0; j < 4; j++) wmma::fill_fragment(cf[j], 0.0f);

    #pragma unroll
    for (int k8 = 0; k8 < 8; k8++) {
        wmma::fragment<wmma::matrix_a, 16, 16, 16, __half, wmma::row_major> af;
        wmma::load_matrix_sync(af, As + rg * 16 * 128 + k8 * 16, 128);
        #pragma unroll
        for (int j = 0; j < 4; j++) {
            wmma::fragment<wmma::matrix_b, 16, 16, 16, __half, wmma::row_major> bf;
            wmma::load_matrix_sync(bf, Bs + k8 * 16 * 128 + ch * 64 + j * 16, 128);
            wmma::mma_sync(cf[j], af, bf, cf[j]);
        }
    }
    __syncthreads();   // done reading As/Bs

    #pragma unroll
    for (int j = 0; j < 4; j++)
        wmma::store_matrix_sync(Cs + rg * 16 * 136 + ch * 64 + j * 16, cf[j],
                                136, wmma::mem_row_major);
    __syncthreads();

    // epilogue: 4 threads per row; quad q covers cols q*32..q*32+31
    int row = tid >> 2;
    int q = tid & 3;
    int m = m0 + row;
    const float* crow = Cs + row * 136 + q * 32;
    float ps = 0.0f, pd = 0.0f;
    #pragma unroll
    for (int c = 0; c < 32; c += 2) {
        float c0 = crow[c], c1 = crow[c + 1];
        int col = q * 32 + c;
        ps += c0 * a1[col]      + c1 * a1[col + 1];
        pd += c0 * a1[F1 + col] + c1 * a1[F1 + col + 1];
        *(__half2*)&g_h1h[(size_t)m * F1 + col] = __floats2half2_rn(c0, c1);
    }
    ps += __shfl_xor_sync(0xffffffffu, ps, 1);
    pd += __shfl_xor_sync(0xffffffffu, pd, 1);
    ps += __shfl_xor_sync(0xffffffffu, ps, 2);
    pd += __shfl_xor_sync(0xffffffffu, pd, 2);
    if (q == 0) { g_ssrc1[m] = ps; g_sdst1[m] = pd; }
}

// ---------------- attention layer 1 + sigmoid gate -----------------------
__global__ void att1_kernel(const float* __restrict__ state) {
    int bi = blockIdx.x;
    int b = bi >> 10;
    int i = bi & (NN - 1);
    int tid = threadIdx.x;          // 0..63
    __shared__ float w[MAXD];
    __shared__ int   js[MAXD];
    __shared__ float red[4];

    int deg = g_deg[i];
    float si = g_ssrc1[b * NN + i];
    float e0 = -3.0e38f, e1 = -3.0e38f;
    if (tid < deg) {
        int j = g_nbr[i * MAXD + tid];
        js[tid] = j;
        float x = si + g_sdst1[b * NN + j];
        e0 = (x > 0.0f) ? x : ALPHA * x;
    }
    int t1 = tid + 64;
    if (t1 < deg) {
        int j = g_nbr[i * MAXD + t1];
        js[t1] = j;
        float x = si + g_sdst1[b * NN + j];
        e1 = (x > 0.0f) ? x : ALPHA * x;
    }
    float mx = fmaxf(e0, e1);
    #pragma unroll
    for (int o = 16; o; o >>= 1) mx = fmaxf(mx, __shfl_xor_sync(0xffffffffu, mx, o));
    if ((tid & 31) == 0) red[tid >> 5] = mx;
    __syncthreads();
    mx = fmaxf(red[0], red[1]);

    float w0 = (tid < deg) ? expf(e0 - mx) : 0.0f;
    float w1 = (t1  < deg) ? expf(e1 - mx) : 0.0f;
    w[tid] = w0;
    if (t1 < deg) w[t1] = w1;
    float sm = w0 + w1;
    #pragma unroll
    for (int o = 16; o; o >>= 1) sm += __shfl_xor_sync(0xffffffffu, sm, o);
    if ((tid & 31) == 0) red[2 + (tid >> 5)] = sm;
    __syncthreads();
    float inv = 1.0f / (red[2] + red[3]);

    const __half2* hb = (const __half2*)g_h1h + (size_t)b * NN * 64 + tid;
    float ax = 0.0f, ay = 0.0f;
    int t = 0;
    for (; t + 4 <= deg; t += 4) {
        float ww0 = w[t],  ww1 = w[t+1], ww2 = w[t+2], ww3 = w[t+3];
        int ja = js[t], jb = js[t+1], jc = js[t+2], jd = js[t+3];
        float2 f0 = __half22float2(hb[(size_t)ja * 64]);
        float2 f1 = __half22float2(hb[(size_t)jb * 64]);
        float2 f2 = __half22float2(hb[(size_t)jc * 64]);
        float2 f3 = __half22float2(hb[(size_t)jd * 64]);
        ax += ww0*f0.x + ww1*f1.x + ww2*f2.x + ww3*f3.x;
        ay += ww0*f0.y + ww1*f1.y + ww2*f2.y + ww3*f3.y;
    }
    for (; t < deg; t++) {
        float ww = w[t];
        float2 f = __half22float2(hb[(size_t)js[t] * 64]);
        ax += ww * f.x;
        ay += ww * f.y;
    }
    ax *= inv; ay *= inv;
    float g0 = 1.0f / (1.0f + expf(-ax));
    float g1 = 1.0f / (1.0f + expf(-ay));

    int m = b * NN + i;
    if (tid < 32) {
        float2 st = *(const float2*)&state[(size_t)m * UU + 2 * tid];
        float2 r2 = make_float2(g0 * st.x, g1 * st.y);
        *(float2*)&g_rstate[(size_t)m * UU + 2 * tid] = r2;
    } else {
        float2 z2 = make_float2(g0, g1);
        *(float2*)&g_z[(size_t)m * UU + 2 * (tid - 32)] = z2;
    }
}

// ---------------- GEMM2 (HMMA): h2[128x64 tile] = [X|r*state] @ W2 -------
// 256 threads, 8 warps. warp w: rows w*16, cols 0..63 (4 frags).
// smem: A 128x128 half (32KB) + B 128x64 half (16KB) = 48KB; C reuses it.
__global__ void gemm2_kernel(const float* __restrict__ X,
                             const float* __restrict__ W2,
                             const float* __restrict__ a2) {
    __shared__ __align__(16) char smem[49152];
    __half* As = (__half*)smem;                 // [128][128]
    __half* Bs = (__half*)(smem + 32768);       // [128][64]
    float*  Cs = (float*)smem;                  // [128][72] after sync

    int tid = threadIdx.x;
    int m0 = blockIdx.x * 128;

    // stage A: 4096 float4 slots
    #pragma unroll
    for (int i = 0; i < 16; i++) {
        int idx = tid + 256 * i;
        int r = idx >> 5, s = idx & 31;
        int k0 = s * 4;
        int m = m0 + r;
        float4 v = (k0 < 64) ? *(const float4*)&X[(size_t)m * 64 + k0]
                             : *(const float4*)&g_rstate[(size_t)m * 64 + k0 - 64];
        __half2* dst = (__half2*)&As[r * 128 + k0];
        dst[0] = __floats2half2_rn(v.x, v.y);
        dst[1] = __floats2half2_rn(v.z, v.w);
    }
    // stage B: 2048 float4 slots
    #pragma unroll
    for (int i = 0; i < 8; i++) {
        int idx = tid + 256 * i;
        int kk = idx >> 4, s = idx & 15;
        int n0 = s * 4;
        float4 v = *(const float4*)&W2[(size_t)kk * 64 + n0];
        __half2* dst = (__half2*)&Bs[kk * 64 + n0];
        dst[0] = __floats2half2_rn(v.x, v.y);
        dst[1] = __floats2half2_rn(v.z, v.w);
    }
    __syncthreads();

    int w = tid >> 5;

    wmma::fragment<wmma::accumulator, 16, 16, 16, float> cf[4];
    #pragma unroll
    for (int j = 0; j < 4; j++) wmma::fill_fragment(cf[j], 0.0f);

    #pragma unroll
    for (int k8 = 0; k8 < 8; k8++) {
        wmma::fragment<wmma::matrix_a, 16, 16, 16, __half, wmma::row_major> af;
        wmma::load_matrix_sync(af, As + w * 16 * 128 + k8 * 16, 128);
        #pragma unroll
        for (int j = 0; j < 4; j++) {
            wmma::fragment<wmma::matrix_b, 16, 16, 16, __half, wmma::row_major> bf;
            wmma::load_matrix_sync(bf, Bs + k8 * 16 * 64 + j * 16, 64);
            wmma::mma_sync(cf[j], af, bf, cf[j]);
        }
    }
    __syncthreads();

    #pragma unroll
    for (int j = 0; j < 4; j++)
        wmma::store_matrix_sync(Cs + w * 16 * 72 + j * 16, cf[j],
                                72, wmma::mem_row_major);
    __syncthreads();

    // epilogue: 2 threads per row; half hh covers cols hh*32..hh*32+31
    int row = tid >> 1;
    int hh = tid & 1;
    int m = m0 + row;
    const float* crow = Cs + row * 72 + hh * 32;
    float ps = 0.0f, pd = 0.0f;
    #pragma unroll
    for (int c = 0; c < 32; c += 2) {
        float c0 = crow[c], c1 = crow[c + 1];
        int col = hh * 32 + c;
        ps += c0 * a2[col]      + c1 * a2[col + 1];
        pd += c0 * a2[UU + col] + c1 * a2[UU + col + 1];
        *(__half2*)&g_h2h[(size_t)m * UU + col] = __floats2half2_rn(c0, c1);
    }
    ps += __shfl_xor_sync(0xffffffffu, ps, 1);
    pd += __shfl_xor_sync(0xffffffffu, pd, 1);
    if (hh == 0) { g_ssrc2[m] = ps; g_sdst2[m] = pd; }
}

// ---------------- attention layer 2 + tanh + GRU blend -------------------
__global__ void att2_kernel(const float* __restrict__ state,
                            float* __restrict__ out) {
    int bi = blockIdx.x;
    int b = bi >> 10;
    int i = bi & (NN - 1);
    int tid = threadIdx.x;          // 0..63
    __shared__ float w[MAXD];
    __shared__ int   js[MAXD];
    __shared__ float red[4];

    int deg = g_deg[i];
    float si = g_ssrc2[b * NN + i];
    float e0 = -3.0e38f, e1 = -3.0e38f;
    if (tid < deg) {
        int j = g_nbr[i * MAXD + tid];
        js[tid] = j;
        float x = si + g_sdst2[b * NN + j];
        e0 = (x > 0.0f) ? x : ALPHA * x;
    }
    int t1 = tid + 64;
    if (t1 < deg) {
        int j = g_nbr[i * MAXD + t1];
        js[t1] = j;
        float x = si + g_sdst2[b * NN + j];
        e1 = (x > 0.0f) ? x : ALPHA * x;
    }
    float mx = fmaxf(e0, e1);
    #pragma unroll
    for (int o = 16; o; o >>= 1) mx = fmaxf(mx, __shfl_xor_sync(0xffffffffu, mx, o));
    if ((tid & 31) == 0) red[tid >> 5] = mx;
    __syncthreads();
    mx = fmaxf(red[0], red[1]);

    float w0 = (tid < deg) ? expf(e0 - mx) : 0.0f;
    float w1 = (t1  < deg) ? expf(e1 - mx) : 0.0f;
    w[tid] = w0;
    if (t1 < deg) w[t1] = w1;
    float sm = w0 + w1;
    #pragma unroll
    for (int o = 16; o; o >>= 1) sm += __shfl_xor_sync(0xffffffffu, sm, o);
    if ((tid & 31) == 0) red[2 + (tid >> 5)] = sm;
    __syncthreads();
    float inv = 1.0f / (red[2] + red[3]);

    if (tid < 32) {
        const __half2* hb = (const __half2*)g_h2h + (size_t)b * NN * 32 + tid;
        float ax = 0.0f, ay = 0.0f;
        int t = 0;
        for (; t + 4 <= deg; t += 4) {
            float ww0 = w[t], ww1 = w[t+1], ww2 = w[t+2], ww3 = w[t+3];
            int ja = js[t], jb = js[t+1], jc = js[t+2], jd = js[t+3];
            float2 f0 = __half22float2(hb[(size_t)ja * 32]);
            float2 f1 = __half22float2(hb[(size_t)jb * 32]);
            float2 f2 = __half22float2(hb[(size_t)jc * 32]);
            float2 f3 = __half22float2(hb[(size_t)jd * 32]);
            ax += ww0*f0.x + ww1*f1.x + ww2*f2.x + ww3*f3.x;
            ay += ww0*f0.y + ww1*f1.y + ww2*f2.y + ww3*f3.y;
        }
        for (; t < deg; t++) {
            float ww = w[t];
            float2 f = __half22float2(hb[(size_t)js[t] * 32]);
            ax += ww * f.x;
            ay += ww * f.y;
        }
        ax *= inv; ay *= inv;
        float h0 = tanhf(ax);
        float h1v = tanhf(ay);

        int m = b * NN + i;
        float2 st = *(const float2*)&state[(size_t)m * UU + 2 * tid];
        float2 z2 = *(const float2*)&g_z[(size_t)m * UU + 2 * tid];
        float2 o2;
        o2.x = z2.x * st.x + (1.0f - z2.x) * h0;
        o2.y = z2.y * st.y + (1.0f - z2.y) * h1v;
        *(float2*)&out[(size_t)m * UU + 2 * tid] = o2;
    }
}

// ---------------- launch -------------------------------------------------
extern "C" void kernel_launch(void* const* d_in, const int* in_sizes, int n_in,
                              void* d_out, int out_size) {
    const float* X     = (const float*)d_in[0];
    const float* state = (const float*)d_in[1];
    const float* adj   = (const float*)d_in[2];
    const float* W1    = (const float*)d_in[3];
    const float* a1    = (const float*)d_in[4];
    const float* W2    = (const float*)d_in[5];
    const float* a2    = (const float*)d_in[6];
    float* out = (float*)d_out;

    build_adj_kernel<<<NN / 8, 256>>>(adj);
    gemm1_kernel<<<MTOT / 64, 256>>>(X, state, W1, a1);
    att1_kernel<<<MTOT, 64>>>(state);
    gemm2_kernel<<<MTOT / 128, 256>>>(X, W2, a2);
    att2_kernel<<<MTOT, 64>>>(state, out);
}